// round 13
// baseline (speedup 1.0000x reference)
#include <cuda_runtime.h>

#define NCLS 19
#define FPX  16384      // 128*128 feature pixels
#define DCH  64
#define LBL  512
#define SCH  64         // list chunks (grid.y of mom/kde)
#define NTP  256
#define PADQ 1024       // list pad quantum -> chunk len multiple of 16
#define CHPX 8192

__device__ unsigned char g_cnt8[NCLS * FPX];
__device__ unsigned int  g_pairs[NCLS * FPX];   // (w<<16)|pixel, zero-padded
__device__ int           g_len[NCLS];
__device__ float         g_n[NCLS];
__device__ float         g_ft[FPX * DCH];       // transposed feature [p][d]
__device__ float         g_m1p[NCLS * DCH * SCH];       // [cls][ch][s]
__device__ float         g_m2p[NCLS * DCH * SCH];       // [cls][ch][s]
__device__ float         g_binp[NCLS * DCH * SCH * 8];  // [cls][ch][sb][8]
__device__ float         g_closs[NCLS];
__device__ int           g_ctick[NCLS];
__device__ int           g_gtick;

typedef unsigned long long ull;

__device__ __forceinline__ float ex2f(float x) {
    float y; asm("ex2.approx.ftz.f32 %0, %1;" : "=f"(y) : "f"(x)); return y;
}
__device__ __forceinline__ ull pk2(float lo, float hi) {
    ull r; asm("mov.b64 %0, {%1, %2};" : "=l"(r) : "f"(lo), "f"(hi)); return r;
}
__device__ __forceinline__ ull pkb(unsigned lo, unsigned hi) {
    ull r; asm("mov.b64 %0, {%1, %2};" : "=l"(r) : "r"(lo), "r"(hi)); return r;
}
__device__ __forceinline__ void upk2(float& lo, float& hi, ull v) {
    asm("mov.b64 {%0, %1}, %2;" : "=f"(lo), "=f"(hi) : "l"(v));
}
__device__ __forceinline__ ull fma2(ull a, ull b, ull c) {
    ull d; asm("fma.rn.f32x2 %0, %1, %2, %3;" : "=l"(d) : "l"(a), "l"(b), "l"(c)); return d;
}
__device__ __forceinline__ ull mul2(ull a, ull b) {
    ull d; asm("mul.rn.f32x2 %0, %1, %2;" : "=l"(d) : "l"(a), "l"(b)); return d;
}

// recurrence constants (exponent -12.5(k-t)^2 in base 2):
#define CLK  (-18.033688011112042f)    // -12.5*log2(e)
#define RA   (-36.06737602222409f)     // -25*log2(e)
#define RB   (90.16844005556021f)      //  62.5*log2(e)
#define CC1  (1.3887943864964021e-11f) // exp(-25)
#define CC2  (1.9287498479639178e-22f) // exp(-50)
#define CC3  (2.6786369618080778e-33f) // exp(-75)

// ───── K0: prep = feature transpose (blocks 0..255) + label counts (256..319)
__global__ __launch_bounds__(256) void prep_kernel(const float* __restrict__ feat,
                                                   const int* __restrict__ label) {
    __shared__ float sm[64][65];
    const int bi = blockIdx.x, tid = threadIdx.x;
    if (bi < 256) {
        const int pixbase = bi * 64;
        const int sub = tid >> 6, low = tid & 63;
#pragma unroll
        for (int it = 0; it < 16; it++) {
            int d = sub + it * 4;
            sm[d][low] = feat[d * FPX + pixbase + low];
        }
        __syncthreads();
#pragma unroll
        for (int it = 0; it < 16; it++) {
            int p_off = sub + it * 4;
            g_ft[(pixbase + p_off) * 64 + low] = sm[low][p_off];
        }
    } else {
        const int fp = (bi - 256) * 256 + tid;
        const int r = fp >> 7, c = fp & 127;
        const int4* lp = reinterpret_cast<const int4*>(label + (r * 4) * LBL + c * 4);
        unsigned pk[4];
#pragma unroll
        for (int dr = 0; dr < 4; dr++) {
            int4 v = lp[dr * (LBL / 4)];
            pk[dr] = (unsigned)v.x | ((unsigned)v.y << 8) |
                     ((unsigned)v.z << 16) | ((unsigned)v.w << 24);
        }
#pragma unroll
        for (int cls = 0; cls < NCLS; cls++) {
            unsigned u = (unsigned)cls * 0x01010101u;
            int s = 0;
#pragma unroll
            for (int dr = 0; dr < 4; dr++)
                s = __dp4a((int)(__vcmpeq4(pk[dr], u) & 0x01010101u), 0x01010101, s);
            g_cnt8[cls * FPX + fp] = (unsigned char)s;
        }
    }
}

// ───── K1: ordered compaction (one block per class)
__global__ __launch_bounds__(NTP) void compact_kernel() {
    const int cls = blockIdx.x;
    const int tid = threadIdx.x, lane = tid & 31, wid = tid >> 5;
    __shared__ unsigned sbuf[CHPX];
    __shared__ unsigned wtot[8], wbase[8];
    __shared__ int wsumw[8];
    __shared__ unsigned chtot_s;
    __shared__ int nacc_s;

    if (tid == 0) nacc_s = 0;
    unsigned gbase = 0;
    unsigned int* __restrict__ out = g_pairs + cls * FPX;

    for (int h = 0; h < FPX / CHPX; h++) {
        const int pxbase = h * CHPX + tid * 32;
        unsigned d[8];
        const uint4* src = reinterpret_cast<const uint4*>(g_cnt8 + cls * FPX + h * CHPX)
                           + tid * 2;
        uint4 v0 = src[0], v1 = src[1];
        d[0]=v0.x; d[1]=v0.y; d[2]=v0.z; d[3]=v0.w;
        d[4]=v1.x; d[5]=v1.y; d[6]=v1.z; d[7]=v1.w;

        int nnz = 0, ws = 0;
#pragma unroll
        for (int j = 0; j < 8; j++) {
            unsigned u = d[j];
            nnz += __popc(__vcmpne4(u, 0u) & 0x01010101u);
            ws  += __dp4a((int)u, 0x01010101, 0);
        }
        unsigned inc = (unsigned)nnz;
#pragma unroll
        for (int o = 1; o < 32; o <<= 1) {
            unsigned t = __shfl_up_sync(0xffffffffu, inc, o);
            if (lane >= o) inc += t;
        }
        if (lane == 31) wtot[wid] = inc;
        int wsr = ws;
#pragma unroll
        for (int o = 16; o; o >>= 1) wsr += __shfl_xor_sync(0xffffffffu, wsr, o);
        if (lane == 0) wsumw[wid] = wsr;
        __syncthreads();
        if (tid == 0) {
            unsigned run = 0; int ns = 0;
#pragma unroll
            for (int j = 0; j < 8; j++) { wbase[j] = run; run += wtot[j]; ns += wsumw[j]; }
            chtot_s = run;
            nacc_s += ns;
        }
        __syncthreads();

        unsigned rank = wbase[wid] + inc - (unsigned)nnz;
#pragma unroll
        for (int j = 0; j < 8; j++) {
            unsigned u = d[j];
#pragma unroll
            for (int b = 0; b < 4; b++) {
                unsigned w = (u >> (8 * b)) & 0xffu;
                if (w) sbuf[rank++] = (w << 16) | (unsigned)(pxbase + j * 4 + b);
            }
        }
        __syncthreads();
        unsigned chtot = chtot_s;
        for (unsigned j = tid; j < chtot; j += NTP) out[gbase + j] = sbuf[j];
        gbase += chtot;
        __syncthreads();
    }
    unsigned pl = (gbase + PADQ - 1) / PADQ * PADQ;
    for (unsigned k = gbase + tid; k < pl; k += NTP) out[k] = 0u;
    if (tid == 0) { g_len[cls] = (int)pl; g_n[cls] = (float)nacc_s; }
}

// ───── K2: partial moments per (class, chunk), contiguous entries.
__global__ __launch_bounds__(256) void mom_kernel() {
    const int cls = blockIdx.x, s = blockIdx.y;
    if (g_n[cls] < 1000.0f) return;
    const int tid = threadIdx.x, lane = tid & 31, wid = tid >> 5;
    const int clen = g_len[cls] >> 6;          // multiple of 16
    const unsigned* __restrict__ pe = g_pairs + cls * FPX + s * clen;
    const float2* __restrict__ ft2 = reinterpret_cast<const float2*>(g_ft);

    ull s1 = 0ull, s2 = 0ull;
    for (int i = 2 * wid; i < clen; i += 16) {
        unsigned pa = __ldg(pe + i);
        unsigned pb = __ldg(pe + i + 1);
        float2 fa = ft2[(pa & 0xFFFFu) * 32 + lane];
        float2 fc = ft2[(pb & 0xFFFFu) * 32 + lane];
        float wa = (float)(pa >> 16), wb = (float)(pb >> 16);
        ull fa2 = pk2(fa.x, fa.y), fc2 = pk2(fc.x, fc.y);
        ull wa2 = pk2(wa, wa),     wb2 = pk2(wb, wb);
        s1 = fma2(fa2, wa2, s1);
        s2 = fma2(mul2(fa2, fa2), wa2, s2);
        s1 = fma2(fc2, wb2, s1);
        s2 = fma2(mul2(fc2, fc2), wb2, s2);
    }
    __shared__ float2 sm1[8][32], sm2[8][32];
    float l1, h1, l2, h2;
    upk2(l1, h1, s1); upk2(l2, h2, s2);
    sm1[wid][lane] = make_float2(l1, h1);
    sm2[wid][lane] = make_float2(l2, h2);
    __syncthreads();
    if (tid < 32) {
        float a = 0.f, b = 0.f, c = 0.f, d = 0.f;
#pragma unroll
        for (int w = 0; w < 8; w++) {
            a += sm1[w][tid].x; b += sm1[w][tid].y;
            c += sm2[w][tid].x; d += sm2[w][tid].y;
        }
        g_m1p[(cls * DCH + 2 * tid) * SCH + s]     = a;
        g_m1p[(cls * DCH + 2 * tid + 1) * SCH + s] = b;
        g_m2p[(cls * DCH + 2 * tid) * SCH + s]     = c;
        g_m2p[(cls * DCH + 2 * tid + 1) * SCH + s] = d;
    }
}

// per-entry header: t -> (g at near end, ratio r, signed weight banks)
__device__ __forceinline__ void hdr5(unsigned pv, float2 fv, ull invs2, ull nmu2,
                                     ull& g, ull& r, ull& wp, ull& wn) {
    ull t2 = fma2(pk2(fv.x, fv.y), invs2, nmu2);
    float t0, t1; upk2(t0, t1, t2);
    float a0 = fabsf(t0), a1 = fabsf(t1);
    float x0 = 3.0f - a0, x1 = 3.0f - a1;
    g = pk2(ex2f(fmaf(CLK * x0, x0, 100.0f)), ex2f(fmaf(CLK * x1, x1, 100.0f)));
    r = pk2(ex2f(fmaf(RA, a0, RB)), ex2f(fmaf(RA, a1, RB)));
    unsigned m0 = (unsigned)(__float_as_int(t0) >> 31);
    unsigned m1 = (unsigned)(__float_as_int(t1) >> 31);
    unsigned wb = __float_as_uint((float)(pv >> 16));
    wp = pkb(wb & ~m0, wb & ~m1);
    wn = pkb(wb &  m0, wb &  m1);
}

// ───── K3: 5-bin recurrence KDE over contiguous chunks.
__global__ __launch_bounds__(128, 6) void kde_kernel(float* __restrict__ outp) {
    const int cls = blockIdx.x, sb = blockIdx.y;
    const int tid = threadIdx.x, lane = tid & 31, wid = tid >> 5;
    const float n = g_n[cls];
    const bool active = (n >= 1000.0f);

    __shared__ float sinv[DCH], snmu[DCH];
    __shared__ float2 stgP[4][32][5], stgN[4][32][5];
    __shared__ float red[4];
    __shared__ int sflag, gflag;

    if (active && tid < DCH) {
        const float4* m1 = reinterpret_cast<const float4*>(g_m1p + (cls * DCH + tid) * SCH);
        const float4* m2 = reinterpret_cast<const float4*>(g_m2p + (cls * DCH + tid) * SCH);
        float S1 = 0.f, S2 = 0.f;
#pragma unroll
        for (int s = 0; s < SCH / 4; s++) {
            float4 a = m1[s]; S1 += (a.x + a.y) + (a.z + a.w);
            float4 b = m2[s]; S2 += (b.x + b.y) + (b.z + b.w);
        }
        float nsafe = fmaxf(n, 1.0f);
        float miu = S1 / nsafe;
        float var = fmaxf(S2 / nsafe - miu * miu, 0.0f) + 1e-10f;
        float invs = rsqrtf(var);
        sinv[tid] = invs;
        snmu[tid] = -miu * invs;
    }
    __syncthreads();

    if (active) {
        const int clen = g_len[cls] >> 6;      // multiple of 16
        const int qlen = clen >> 2;            // per-warp, multiple of 4
        const unsigned* __restrict__ pe = g_pairs + cls * FPX + sb * clen + wid * qlen;
        const float2* __restrict__ ft2 = reinterpret_cast<const float2*>(g_ft);
        const ull invs2 = pk2(sinv[2 * lane], sinv[2 * lane + 1]);
        const ull nmu2  = pk2(snmu[2 * lane], snmu[2 * lane + 1]);
        const ull cc1_2 = pk2(CC1, CC1);
        const ull cc2_2 = pk2(CC2, CC2);
        const ull cc3_2 = pk2(CC3, CC3);
        ull accP[5], accN[5];
#pragma unroll
        for (int k = 0; k < 5; k++) { accP[k] = 0ull; accN[k] = 0ull; }

#pragma unroll 2
        for (int i = 0; i < qlen; i += 2) {
            unsigned pv0 = __ldg(pe + i);           // broadcast
            unsigned pv1 = __ldg(pe + i + 1);
            float2 fv0 = ft2[(pv0 & 0xFFFFu) * 32 + lane];
            float2 fv1 = ft2[(pv1 & 0xFFFFu) * 32 + lane];
            ull g0, r0, wp0, wn0, g1, r1, wp1, wn1;
            hdr5(pv0, fv0, invs2, nmu2, g0, r0, wp0, wn0);
            hdr5(pv1, fv1, invs2, nmu2, g1, r1, wp1, wn1);
            // parallel ratio ladder (short critical path)
            ull r0b = mul2(r0, cc1_2), r0c = mul2(r0, cc2_2), r0d = mul2(r0, cc3_2);
            ull r1b = mul2(r1, cc1_2), r1c = mul2(r1, cc2_2), r1d = mul2(r1, cc3_2);
            accP[0] = fma2(wp0, g0, accP[0]); accN[0] = fma2(wn0, g0, accN[0]);
            accP[0] = fma2(wp1, g1, accP[0]); accN[0] = fma2(wn1, g1, accN[0]);
            g0 = mul2(g0, r0);  g1 = mul2(g1, r1);
            accP[1] = fma2(wp0, g0, accP[1]); accN[1] = fma2(wn0, g0, accN[1]);
            accP[1] = fma2(wp1, g1, accP[1]); accN[1] = fma2(wn1, g1, accN[1]);
            g0 = mul2(g0, r0b); g1 = mul2(g1, r1b);
            accP[2] = fma2(wp0, g0, accP[2]); accN[2] = fma2(wn0, g0, accN[2]);
            accP[2] = fma2(wp1, g1, accP[2]); accN[2] = fma2(wn1, g1, accN[2]);
            g0 = mul2(g0, r0c); g1 = mul2(g1, r1c);
            accP[3] = fma2(wp0, g0, accP[3]); accN[3] = fma2(wn0, g0, accN[3]);
            accP[3] = fma2(wp1, g1, accP[3]); accN[3] = fma2(wn1, g1, accN[3]);
            g0 = mul2(g0, r0d); g1 = mul2(g1, r1d);
            accP[4] = fma2(wp0, g0, accP[4]); accN[4] = fma2(wn0, g0, accN[4]);
            accP[4] = fma2(wp1, g1, accP[4]); accN[4] = fma2(wn1, g1, accN[4]);
        }
#pragma unroll
        for (int k = 0; k < 5; k++) {
            float lo, hi;
            upk2(lo, hi, accP[k]); stgP[wid][lane][k] = make_float2(lo, hi);
            upk2(lo, hi, accN[k]); stgN[wid][lane][k] = make_float2(lo, hi);
        }
    }
    __syncthreads();

    if (active && tid < DCH) {
        const int pi = tid >> 1, comp = tid & 1;
        float P[5], N[5];
#pragma unroll
        for (int k = 0; k < 5; k++) {
            float vP = 0.f, vN = 0.f;
#pragma unroll
            for (int w = 0; w < 4; w++) {
                float2 p2 = stgP[w][pi][k], n2 = stgN[w][pi][k];
                vP += comp ? p2.y : p2.x;
                vN += comp ? n2.y : n2.x;
            }
            P[k] = vP; N[k] = vN;
        }
        // bin[j] = (j>=2 ? P[6-j] : 0) + (j<=4 ? N[j] : 0)
        float4* bp = reinterpret_cast<float4*>(g_binp + ((cls * DCH + tid) * SCH + sb) * 8);
        bp[0] = make_float4(N[0], N[1], P[4] + N[2], P[3] + N[3]);
        bp[1] = make_float4(P[2] + N[4], P[1], P[0], 0.f);
    }
    __threadfence();
    if (tid == 0) {
        int t = atomicAdd(&g_ctick[cls], 1);
        sflag = (t == SCH - 1) ? 1 : 0;
    }
    __syncthreads();

    if (sflag) {
        __threadfence();
        float myloss = 0.f;
        if (active && tid < DCH) {
            float sbin[7] = {0.f, 0.f, 0.f, 0.f, 0.f, 0.f, 0.f};
            const float4* bp = reinterpret_cast<const float4*>(g_binp + (cls * DCH + tid) * SCH * 8);
            for (int s = 0; s < SCH; s++) {
                float4 v0 = bp[2 * s], v1 = bp[2 * s + 1];
                sbin[0] += v0.x; sbin[1] += v0.y; sbin[2] += v0.z; sbin[3] += v0.w;
                sbin[4] += v1.x; sbin[5] += v1.y; sbin[6] += v1.z;
            }
            float tot = 0.f;
#pragma unroll
            for (int ib = 0; ib < 7; ib++) tot += sbin[ib];
            float inv = 1.0f / fmaxf(tot, 1e-30f);
            const float targ[7] = {0.00443305f, 0.05400558f, 0.24203623f, 0.39905027f,
                                   0.24203623f, 0.05400558f, 0.00443305f};
            float L = 0.f;
#pragma unroll
            for (int ib = 0; ib < 7; ib++) {
                float dif = fabsf(sbin[ib] * inv - targ[ib]);
                L += (dif < 1.0f) ? 0.5f * dif * dif : (dif - 0.5f);
            }
            myloss = L;
        }
        float v = myloss;
#pragma unroll
        for (int o = 16; o; o >>= 1) v += __shfl_xor_sync(0xffffffffu, v, o);
        if (lane == 0) red[wid] = v;
        __syncthreads();
        if (tid == 0) {
            float sum = red[0] + red[1] + red[2] + red[3];
            g_closs[cls] = active ? sum * (1.0f / (7.0f * (float)DCH)) : 0.f;
            g_ctick[cls] = 0;   // reset for next graph replay
            __threadfence();
            int gt = atomicAdd(&g_gtick, 1);
            gflag = (gt == NCLS - 1) ? 1 : 0;
        }
        __syncthreads();
        if (gflag && tid == 0) {
            __threadfence();
            float num = 0.f, den = 0.f;
#pragma unroll
            for (int c = 0; c < NCLS; c++) {
                num += g_closs[c];
                den += (g_n[c] >= 1000.0f) ? 1.0f : 0.0f;
            }
            outp[0] = num / den;
            g_gtick = 0;        // reset for next graph replay
        }
    }
}

extern "C" void kernel_launch(void* const* d_in, const int* in_sizes, int n_in,
                              void* d_out, int out_size) {
    const float* feature;
    const int*   label;
    if (in_sizes[0] == DCH * FPX) {
        feature = (const float*)d_in[0];
        label   = (const int*)d_in[1];
    } else {
        feature = (const float*)d_in[1];
        label   = (const int*)d_in[0];
    }
    prep_kernel<<<320, 256>>>(feature, label);
    compact_kernel<<<NCLS, NTP>>>();
    mom_kernel<<<dim3(NCLS, SCH), 256>>>();
    kde_kernel<<<dim3(NCLS, SCH), 128>>>((float*)d_out);
}

// round 15
// speedup vs baseline: 1.6632x; 1.6632x over previous
#include <cuda_runtime.h>

#define NCLS 19
#define FPX  16384      // 128*128 feature pixels
#define DCH  64
#define LBL  512
#define NT   256

__device__ unsigned char g_cnt8[NCLS * FPX];   // per-class per-pixel weights (0..16)
__device__ float g_loss[NCLS * DCH];
__device__ float g_n[NCLS];
__device__ unsigned g_tick;

typedef unsigned long long ull;

__device__ __forceinline__ float ex2f(float x) {
    float y; asm("ex2.approx.ftz.f32 %0, %1;" : "=f"(y) : "f"(x)); return y;
}
__device__ __forceinline__ ull pk2(float lo, float hi) {
    ull r; asm("mov.b64 %0, {%1, %2};" : "=l"(r) : "f"(lo), "f"(hi)); return r;
}
__device__ __forceinline__ ull pkb(unsigned lo, unsigned hi) {
    ull r; asm("mov.b64 %0, {%1, %2};" : "=l"(r) : "r"(lo), "r"(hi)); return r;
}
__device__ __forceinline__ void upk2(float& lo, float& hi, ull v) {
    asm("mov.b64 {%0, %1}, %2;" : "=f"(lo), "=f"(hi) : "l"(v));
}
__device__ __forceinline__ ull fma2(ull a, ull b, ull c) {
    ull d; asm("fma.rn.f32x2 %0, %1, %2, %3;" : "=l"(d) : "l"(a), "l"(b), "l"(c)); return d;
}
__device__ __forceinline__ ull mul2(ull a, ull b) {
    ull d; asm("mul.rn.f32x2 %0, %1, %2;" : "=l"(d) : "l"(a), "l"(b)); return d;
}

// recurrence constants (exponent -12.5(k-t)^2 in base 2, scaled by 2^100):
#define CLK  (-18.033688011112042f)    // -12.5*log2(e)
#define RA   (-36.06737602222409f)     // -25*log2(e)
#define RB   (90.16844005556021f)      //  62.5*log2(e)
#define CC1  (1.3887943864964021e-11f) // exp(-25)
#define CC2  (1.9287498479639178e-22f) // exp(-50)

// K1: per-(pixel,class) 4x4 counts, register-only SIMD.
__global__ __launch_bounds__(64) void count_kernel(const int* __restrict__ label) {
    const int fp = blockIdx.x * 64 + threadIdx.x;
    const int r = fp >> 7, c = fp & 127;
    const int4* lp = reinterpret_cast<const int4*>(label + (r * 4) * LBL + c * 4);
    unsigned pk[4];
#pragma unroll
    for (int dr = 0; dr < 4; dr++) {
        int4 v = lp[dr * (LBL / 4)];
        pk[dr] = (unsigned)v.x | ((unsigned)v.y << 8) |
                 ((unsigned)v.z << 16) | ((unsigned)v.w << 24);
    }
#pragma unroll
    for (int cls = 0; cls < NCLS; cls++) {
        unsigned u = (unsigned)cls * 0x01010101u;
        int s = 0;
#pragma unroll
        for (int dr = 0; dr < 4; dr++)
            s = __dp4a((int)(__vcmpeq4(pk[dr], u) & 0x01010101u), 0x01010101, s);
        g_cnt8[cls * FPX + fp] = (unsigned char)s;
    }
}

// one packed pixel-pair through the 4-bank recurrence
__device__ __forceinline__ void dopair(float fa, float fc, unsigned wa, unsigned wb,
                                       ull invs2, ull nmu2, ull c1, ull c2,
                                       ull* accP, ull* accN) {
    ull t2 = fma2(pk2(fa, fc), invs2, nmu2);
    float t0, t1; upk2(t0, t1, t2);
    float a0 = fabsf(t0), a1 = fabsf(t1);
    float x0 = 3.0f - a0, x1 = 3.0f - a1;
    float gl = ex2f(fmaf(CLK * x0, x0, 100.0f));
    float gh = ex2f(fmaf(CLK * x1, x1, 100.0f));
    float rl = ex2f(fmaf(RA, a0, RB));
    float rh = ex2f(fmaf(RA, a1, RB));
    unsigned m0 = (unsigned)(__float_as_int(t0) >> 31);
    unsigned m1 = (unsigned)(__float_as_int(t1) >> 31);
    unsigned w0 = __float_as_uint((float)wa);
    unsigned w1 = __float_as_uint((float)wb);
    ull wp = pkb(w0 & ~m0, w1 & ~m1);
    ull wn = pkb(w0 &  m0, w1 &  m1);
    ull g = pk2(gl, gh), r = pk2(rl, rh);
    accP[0] = fma2(wp, g, accP[0]); accN[0] = fma2(wn, g, accN[0]);
    g = mul2(g, r);
    accP[1] = fma2(wp, g, accP[1]); accN[1] = fma2(wn, g, accN[1]);
    g = mul2(g, mul2(r, c1));
    accP[2] = fma2(wp, g, accP[2]); accN[2] = fma2(wn, g, accN[2]);
    g = mul2(g, mul2(r, c2));
    accP[3] = fma2(wp, g, accP[3]); accN[3] = fma2(wn, g, accN[3]);
}

// K2: dense streaming klass. One block per (cls, dd). Moments + 4-bank
// recurrence KDE + per-block loss; last block (ticket) emits the scalar.
__global__ __launch_bounds__(NT) void klass_kernel(const float* __restrict__ feat,
                                                   float* __restrict__ outp) {
    const int cls = blockIdx.x, dd = blockIdx.y;
    const float4* __restrict__ f4 = reinterpret_cast<const float4*>(feat + dd * FPX);
    const uchar4* __restrict__ cb = reinterpret_cast<const uchar4*>(g_cnt8 + cls * FPX);
    const int tid = threadIdx.x, lane = tid & 31, wid = tid >> 5;

    __shared__ float red[11][8];
    __shared__ bool amlast;

    // ---- pass 1: dense streaming moments ----
    float s0 = 0.f, s1 = 0.f, s2 = 0.f;
#pragma unroll 4
    for (int i = tid; i < FPX / 4; i += NT) {
        float4 fv = f4[i];
        uchar4 wv = cb[i];
        float w0 = (float)wv.x, w1 = (float)wv.y, w2 = (float)wv.z, w3 = (float)wv.w;
        s0 += (w0 + w1) + (w2 + w3);
        s1 = fmaf(w0, fv.x, fmaf(w1, fv.y, fmaf(w2, fv.z, fmaf(w3, fv.w, s1))));
        s2 = fmaf(w0 * fv.x, fv.x, fmaf(w1 * fv.y, fv.y,
             fmaf(w2 * fv.z, fv.z, fmaf(w3 * fv.w, fv.w, s2))));
    }
#pragma unroll
    for (int o = 16; o; o >>= 1) {
        s0 += __shfl_xor_sync(0xffffffffu, s0, o);
        s1 += __shfl_xor_sync(0xffffffffu, s1, o);
        s2 += __shfl_xor_sync(0xffffffffu, s2, o);
    }
    if (lane == 0) { red[0][wid] = s0; red[1][wid] = s1; red[2][wid] = s2; }
    __syncthreads();
    float n = 0.f, S1 = 0.f, S2 = 0.f;
#pragma unroll
    for (int j = 0; j < 8; j++) { n += red[0][j]; S1 += red[1][j]; S2 += red[2][j]; }

    float loss = 0.f;
    const bool active = (n >= 1000.0f);
    if (active) {
        float nsafe = fmaxf(n, 1.0f);
        float miu = S1 / nsafe;
        float var = fmaxf(S2 / nsafe - miu * miu, 0.0f) + 1e-10f;
        float invs = rsqrtf(var);
        float nmu  = -miu * invs;

        // ---- pass 2: dense 4-bank recurrence KDE ----
        const ull invs2 = pk2(invs, invs);
        const ull nmu2  = pk2(nmu, nmu);
        const ull c1    = pk2(CC1, CC1);
        const ull c2    = pk2(CC2, CC2);
        ull accP[4] = {0ull, 0ull, 0ull, 0ull};
        ull accN[4] = {0ull, 0ull, 0ull, 0ull};

#pragma unroll 2
        for (int i = tid; i < FPX / 4; i += NT) {
            float4 fv = f4[i];
            uchar4 wv = cb[i];
            dopair(fv.x, fv.y, wv.x, wv.y, invs2, nmu2, c1, c2, accP, accN);
            dopair(fv.z, fv.w, wv.z, wv.w, invs2, nmu2, c1, c2, accP, accN);
        }

        // block-reduce 8 bank sums
        float bank[8];
#pragma unroll
        for (int k = 0; k < 4; k++) {
            float lo, hi;
            upk2(lo, hi, accP[k]); bank[k] = lo + hi;
            upk2(lo, hi, accN[k]); bank[4 + k] = lo + hi;
        }
#pragma unroll
        for (int k = 0; k < 8; k++) {
            float v = bank[k];
#pragma unroll
            for (int o = 16; o; o >>= 1) v += __shfl_xor_sync(0xffffffffu, v, o);
            if (lane == 0) red[3 + k][wid] = v;
        }
        __syncthreads();

        if (tid == 0) {
            float P[4], N[4];
#pragma unroll
            for (int k = 0; k < 4; k++) {
                float vP = 0.f, vN = 0.f;
#pragma unroll
                for (int w = 0; w < 8; w++) { vP += red[3 + k][w]; vN += red[7 + k][w]; }
                P[k] = vP; N[k] = vN;
            }
            // P bank s -> bin 6-s ; N bank s -> bin s (bank 4..6 truncated: <=4e-6 rel)
            float sbin[7];
            sbin[0] = N[0]; sbin[1] = N[1]; sbin[2] = N[2];
            sbin[3] = P[3] + N[3];
            sbin[4] = P[2]; sbin[5] = P[1]; sbin[6] = P[0];
            float tot = 0.f;
#pragma unroll
            for (int ib = 0; ib < 7; ib++) tot += sbin[ib];
            float inv = 1.0f / fmaxf(tot, 1e-30f);
            const float targ[7] = {0.00443305f, 0.05400558f, 0.24203623f, 0.39905027f,
                                   0.24203623f, 0.05400558f, 0.00443305f};
            float L = 0.f;
#pragma unroll
            for (int ib = 0; ib < 7; ib++) {
                float dif = fabsf(sbin[ib] * inv - targ[ib]);
                L += (dif < 1.0f) ? 0.5f * dif * dif : (dif - 0.5f);
            }
            loss = L * (1.0f / (7.0f * (float)DCH));
        }
    }

    if (tid == 0) {
        g_loss[cls * DCH + dd] = loss;
        if (dd == 0) g_n[cls] = n;
    }
    __threadfence();
    if (tid == 0) {
        unsigned t = atomicAdd(&g_tick, 1u);
        amlast = (t == (unsigned)(NCLS * DCH - 1));
    }
    __syncthreads();

    if (amlast) {
        __threadfence();
        float s = 0.f;
        for (int i = tid; i < NCLS * DCH; i += NT) s += g_loss[i];
#pragma unroll
        for (int o = 16; o; o >>= 1) s += __shfl_xor_sync(0xffffffffu, s, o);
        if (lane == 0) red[0][wid] = s;
        __syncthreads();
        if (tid == 0) {
            float num = 0.f;
#pragma unroll
            for (int j = 0; j < 8; j++) num += red[0][j];
            float den = 0.f;
#pragma unroll
            for (int c = 0; c < NCLS; c++) den += (g_n[c] >= 1000.0f) ? 1.0f : 0.0f;
            outp[0] = num / den;
            g_tick = 0u;   // reset for next graph replay
        }
    }
}

extern "C" void kernel_launch(void* const* d_in, const int* in_sizes, int n_in,
                              void* d_out, int out_size) {
    const float* feature;
    const int*   label;
    if (in_sizes[0] == DCH * FPX) {
        feature = (const float*)d_in[0];
        label   = (const int*)d_in[1];
    } else {
        feature = (const float*)d_in[1];
        label   = (const int*)d_in[0];
    }
    count_kernel<<<FPX / 64, 64>>>(label);
    klass_kernel<<<dim3(NCLS, DCH), NT>>>(feature, (float*)d_out);
}